// round 4
// baseline (speedup 1.0000x reference)
#include <cuda_runtime.h>
#include <cuda_fp16.h>
#include <cstdint>
#include <cstring>

#define CB  64
#define CS  2048
#define CT  256
#define RPC 128   // rows per CTA (cluster of 2 splits the reduction dim)
#define GSH 9     // log2 renormalization bias

__device__ float g_logz[CB];
__device__ float g_score[CB];

__device__ __forceinline__ float warp_max(float v) {
#pragma unroll
    for (int o = 16; o > 0; o >>= 1)
        v = fmaxf(v, __shfl_xor_sync(0xffffffffu, v, o));
    return v;
}
__device__ __forceinline__ float warp_sum(float v) {
#pragma unroll
    for (int o = 16; o > 0; o >>= 1)
        v += __shfl_xor_sync(0xffffffffu, v, o);
    return v;
}
__device__ __forceinline__ __half2 u2h2(unsigned u) {
    __half2 h; memcpy(&h, &u, 4); return h;
}
__device__ __forceinline__ uint32_t smem_u32(const void* p) {
    return (uint32_t)__cvta_generic_to_shared((void*)p);
}
__device__ __forceinline__ uint32_t mapa_u32(uint32_t addr, uint32_t rank) {
    uint32_t r;
    asm("mapa.shared::cluster.u32 %0, %1, %2;" : "=r"(r) : "r"(addr), "r"(rank));
    return r;
}
__device__ __forceinline__ void mbar_init(uint32_t addr, uint32_t count) {
    asm volatile("mbarrier.init.shared.b64 [%0], %1;" :: "r"(addr), "r"(count) : "memory");
}
__device__ __forceinline__ void st_cluster_f32(uint32_t addr, float v) {
    asm volatile("st.shared::cluster.f32 [%0], %1;" :: "r"(addr), "f"(v) : "memory");
}
__device__ __forceinline__ void mbar_arrive_cluster(uint32_t addr) {
    asm volatile("mbarrier.arrive.release.cluster.shared::cluster.b64 _, [%0];"
                 :: "r"(addr) : "memory");
}
__device__ __forceinline__ void mbar_wait_cluster(uint32_t mbar, uint32_t parity) {
    asm volatile(
        "{\n\t"
        ".reg .pred P;\n\t"
        "WL_%=:\n\t"
        "mbarrier.try_wait.parity.acquire.cluster.shared::cta.b64 P, [%0], %1;\n\t"
        "@!P bra WL_%=;\n\t"
        "}"
        :: "r"(mbar), "r"(parity) : "memory");
}
__device__ __forceinline__ void cluster_sync_() {
    asm volatile("barrier.cluster.arrive.aligned;" ::: "memory");
    asm volatile("barrier.cluster.wait.aligned;" ::: "memory");
}

// ---------------------------------------------------------------------------
// Forward algorithm, probability space, power-of-2 renorm, 2-CTA cluster per
// batch. Each CTA owns 128 of the 256 reduction rows; per step it computes
// partial dot products for ALL 256 columns, pushes them to the peer via
// DSMEM + remote mbarrier arrive (double-buffered), then both CTAs rebuild
// the identical full p vector (same add order, same sampled exponent).
// ---------------------------------------------------------------------------
__global__ void __launch_bounds__(CT, 1) __cluster_dims__(2, 1, 1)
crf_forward(const float* __restrict__ emissions,
            const float* __restrict__ trans,
            const float* __restrict__ start_t,
            const float* __restrict__ end_t)
{
    __shared__ __align__(16) __half pbuf[2][CT];
    __shared__ __align__(16) float  spart[2][CT];     // written by PEER CTA
    __shared__ __align__(8)  unsigned long long mbar[2];
    __shared__ float wred[8];

    const int j = threadIdx.x;
    const int b = blockIdx.x >> 1;
    const int r = blockIdx.x & 1;          // == cluster_ctarank for (2,1,1)

    if (j == 0) {
        mbar_init(smem_u32(&mbar[0]), CT);
        mbar_init(smem_u32(&mbar[1]), CT);
    }

    // M = exp(trans) fp16, column j, rows [r*128, r*128+128), packed pairs.
    __half2 M[RPC / 2];
#pragma unroll
    for (int q = 0; q < RPC / 2; q++) {
        int row = r * RPC + 2 * q;
        float a0 = __expf(trans[row * CT + j]);
        float a1 = __expf(trans[(row + 1) * CT + j]);
        M[q] = __floats2half2_rn(a0, a1);
    }
    __syncthreads();
    cluster_sync_();                        // peer mbars initialized

    // Peer addresses (rank r^1), precomputed once.
    const uint32_t peer = (uint32_t)(r ^ 1);
    uint32_t ps0 = mapa_u32(smem_u32(&spart[0][0]), peer) + 4u * j;
    uint32_t ps1 = mapa_u32(smem_u32(&spart[1][0]), peer) + 4u * j;
    uint32_t pm0 = mapa_u32(smem_u32(&mbar[0]), peer);
    uint32_t pm1 = mapa_u32(smem_u32(&mbar[1]), peer);
    uint32_t mm0 = smem_u32(&mbar[0]);
    uint32_t mm1 = smem_u32(&mbar[1]);

    const float* em = emissions + (size_t)b * CS * CT;
    float alpha0 = start_t[j] + em[j];

    // One-time block max (identical in both CTAs: same code, same order).
    float wm = warp_max(alpha0);
    if ((j & 31) == 0) wred[j >> 5] = wm;
    __syncthreads();
    float m0 = wred[0];
#pragma unroll
    for (int w = 1; w < 8; w++) m0 = fmaxf(m0, wred[w]);

    float A = __expf(alpha0 - m0);
    int ksum = 0;

    pbuf[0][j] = __float2half_rn(A);
    float e_next = em[CT + j];
    __syncthreads();

    for (int t = 1; t < CS; t++) {
        const int pb = (t - 1) & 1;
        const int cb = t & 1;
        const uint4* p4 = (const uint4*)pbuf[pb];
        float e = e_next;
        int tn = (t + 1 < CS) ? (t + 1) : (CS - 1);
        e_next = __ldg(em + (size_t)tn * CT + j);

        // Partial dot over my 128 rows (uint4 indices r*16 .. r*16+15).
        __half2 z = __float2half2_rn(0.f);
        __half2 a0 = z, a1 = z, a2 = z, a3 = z, a4 = z, a5 = z, a6 = z, a7 = z;
        const int base = r * 16;
#pragma unroll
        for (int c = 0; c < 16; c++) {
            uint4 v = p4[base + c];
            __half2 h0 = u2h2(v.x), h1 = u2h2(v.y);
            __half2 h2 = u2h2(v.z), h3 = u2h2(v.w);
            if (c & 1) {
                a4 = __hfma2(M[4 * c + 0], h0, a4);
                a5 = __hfma2(M[4 * c + 1], h1, a5);
                a6 = __hfma2(M[4 * c + 2], h2, a6);
                a7 = __hfma2(M[4 * c + 3], h3, a7);
            } else {
                a0 = __hfma2(M[4 * c + 0], h0, a0);
                a1 = __hfma2(M[4 * c + 1], h1, a1);
                a2 = __hfma2(M[4 * c + 2], h2, a2);
                a3 = __hfma2(M[4 * c + 3], h3, a3);
            }
        }
        // One HADD2 tree level (bounded: |sums| < 3e4 << 65504), then fp32.
        __half2 b0 = __hadd2(a0, a4), b1 = __hadd2(a1, a5);
        __half2 b2 = __hadd2(a2, a6), b3 = __hadd2(a3, a7);
        float2 f0 = __half22float2(b0), f1 = __half22float2(b1);
        float2 f2 = __half22float2(b2), f3 = __half22float2(b3);
        float s_p = ((f0.x + f0.y) + (f1.x + f1.y))
                  + ((f2.x + f2.y) + (f3.x + f3.y));

        // Ship partial to peer ASAP (transit overlaps the work below).
        st_cluster_f32(cb ? ps1 : ps0, s_p);
        mbar_arrive_cluster(cb ? pm1 : pm0);

        // Shared exponent from a fixed full-range sample of p (identical in
        // both CTAs -> identical scale, zero communication).
        __half2 mx = z;
#pragma unroll
        for (int c = 0; c < 8; c++) mx = __hmax2(mx, u2h2(p4[c * 4].x));
        __half hmx = __hmax(__low2half(mx), __high2half(mx));
        int k = (int)((__half_as_ushort(hmx) >> 10) & 0x1F) - 15;
        float scale = __int_as_float((127 - k - GSH) << 23);
        ksum += k + GSH;

        // Wait for peer partial (parity = ((t-1)>>1)&1 for this buffer).
        mbar_wait_cluster(cb ? mm1 : mm0, ((t - 1) >> 1) & 1);
        float s = s_p + spart[cb][j];

        A = __expf(e) * (s * scale);
        pbuf[cb][j] = __float2half_rn(A);
        __syncthreads();
    }

    // log_z (both CTAs hold identical A; rank 0 writes).
    float v = A * __expf(end_t[j]);
    float ws = warp_sum(v);
    if ((j & 31) == 0) wred[j >> 5] = ws;
    __syncthreads();
    if (j == 0 && r == 0) {
        float tot = 0.f;
#pragma unroll
        for (int w = 0; w < 8; w++) tot += wred[w];
        g_logz[b] = m0 + (float)ksum * 0.693147180559945f + logf(tot);
    }
    cluster_sync_();                        // no CTA exits with peer traffic in flight
}

// ---------------------------------------------------------------------------
// Gold-path score: one CTA per batch.
// ---------------------------------------------------------------------------
__global__ void __launch_bounds__(256)
crf_score(const float* __restrict__ emissions,
          const int*   __restrict__ tags,
          const int*   __restrict__ mask,
          const float* __restrict__ trans,
          const float* __restrict__ start_t,
          const float* __restrict__ end_t)
{
    __shared__ float fred[8];
    __shared__ int   ired[8];
    const int b   = blockIdx.x;
    const int tid = threadIdx.x;
    const int*   tg = tags + b * CS;
    const int*   mk = mask + b * CS;
    const float* em = emissions + (size_t)b * CS * CT;

    float part = 0.f;
    int   msum = 0;
    for (int t = tid; t < CS; t += 256) {
        msum += mk[t];
        if (t >= 1 && mk[t]) {
            int a = tg[t], p = tg[t - 1];
            part += trans[a * CT + p] + em[(size_t)t * CT + a];
        }
    }
    float wsum = warp_sum(part);
#pragma unroll
    for (int o = 16; o > 0; o >>= 1)
        msum += __shfl_xor_sync(0xffffffffu, msum, o);
    if ((tid & 31) == 0) { fred[tid >> 5] = wsum; ired[tid >> 5] = msum; }
    __syncthreads();
    if (tid == 0) {
        float tot = 0.f; int mt = 0;
#pragma unroll
        for (int w = 0; w < 8; w++) { tot += fred[w]; mt += ired[w]; }
        int t0   = tg[0];
        int last = tg[mt - 1];          // seq_end = mask.sum() - 1
        g_score[b] = tot + start_t[t0] + em[t0] + end_t[last];
    }
}

// ---------------------------------------------------------------------------
// Final: mean over batch of (score - logz).
// ---------------------------------------------------------------------------
__global__ void crf_final(float* __restrict__ out)
{
    __shared__ float sred[2];
    int t = threadIdx.x;                // 64 threads
    float v = g_score[t] - g_logz[t];
    float w = warp_sum(v);
    if ((t & 31) == 0) sred[t >> 5] = w;
    __syncthreads();
    if (t == 0) out[0] = (sred[0] + sred[1]) * (1.0f / CB);
}

extern "C" void kernel_launch(void* const* d_in, const int* in_sizes, int n_in,
                              void* d_out, int out_size)
{
    const float* emissions = (const float*)d_in[0];
    const int*   tags      = (const int*)d_in[1];
    const int*   mask      = (const int*)d_in[2];
    const float* trans     = (const float*)d_in[3];
    const float* start_t   = (const float*)d_in[4];
    const float* end_t     = (const float*)d_in[5];
    float* out = (float*)d_out;

    crf_forward<<<2 * CB, CT>>>(emissions, trans, start_t, end_t);
    crf_score<<<CB, 256>>>(emissions, tags, mask, trans, start_t, end_t);
    crf_final<<<1, 64>>>(out);
}